// round 2
// baseline (speedup 1.0000x reference)
#include <cuda_runtime.h>

#define B 512
#define N 512
#define THREADS 256

// Scratch (device globals — no allocation allowed in kernel_launch)
__device__ float      g_row_sum[B];
__device__ long long  g_row_pairs[B];
__device__ int        g_lab_stride;   // 1 = int32 labels, 2 = int64 labels

// ---------------------------------------------------------------------------
// Detect label dtype width. int64 values {0,1} have all-zero high 32-bit
// words; int32 labels have ~half ones at odd word indices.
// ---------------------------------------------------------------------------
__global__ void detect_kernel(const unsigned int* __restrict__ labs) {
    if (threadIdx.x == 0) {
        int stride = 2;
        #pragma unroll 1
        for (int i = 1; i < 256; i += 2) {
            if (labs[i] != 0u) { stride = 1; break; }
        }
        g_lab_stride = stride;
    }
}

// ---------------------------------------------------------------------------
// Per-row kernel: compact negs, bitonic sort, suffix scan, binary search per
// pos. One block per row, 256 threads.
// ---------------------------------------------------------------------------
__global__ void __launch_bounds__(THREADS)
row_kernel(const float* __restrict__ scores, const unsigned int* __restrict__ labels) {
    __shared__ float s_sorted[N];   // sorted neg scores (padded with -FLT_MAX at front)
    __shared__ float s_suf[N];      // inclusive suffix sums of real neg scores
    __shared__ float s_pos[N];      // compacted positive scores
    __shared__ int   s_nneg, s_npos;
    __shared__ int   s_stride;
    __shared__ float s_red[THREADS / 32];

    const int row = blockIdx.x;
    const int tid = threadIdx.x;

    if (tid == 0) { s_nneg = 0; s_npos = 0; s_stride = g_lab_stride; }
    __syncthreads();
    const int stride = s_stride;

    const float* srow = scores + (size_t)row * N;
    const unsigned int* lrow = labels + (size_t)row * N * stride;

    // ---- load + compact (order irrelevant: negs get sorted, pos are summed)
    #pragma unroll
    for (int e = 0; e < 2; e++) {
        int i = tid + e * THREADS;
        float v = srow[i];
        unsigned int lab = lrow[(size_t)i * stride];
        if (lab == 0u) {
            int idx = atomicAdd(&s_nneg, 1);
            s_sorted[idx] = v;
        } else {
            int idx = atomicAdd(&s_npos, 1);
            s_pos[idx] = v;
        }
    }
    __syncthreads();
    const int nneg = s_nneg;
    const int npos = s_npos;
    const int npad = N - nneg;

    // pad front-sorting sentinels
    for (int i = nneg + tid; i < N; i += THREADS) s_sorted[i] = -3.4e38f;
    __syncthreads();

    // ---- bitonic sort ascending (pads sink to the front)
    for (int k = 2; k <= N; k <<= 1) {
        for (int j = k >> 1; j > 0; j >>= 1) {
            #pragma unroll
            for (int e = 0; e < 2; e++) {
                int i = tid + e * THREADS;
                int ixj = i ^ j;
                if (ixj > i) {
                    bool up = ((i & k) == 0);
                    float a = s_sorted[i], b = s_sorted[ixj];
                    if ((a > b) == up) { s_sorted[i] = b; s_sorted[ixj] = a; }
                }
            }
            __syncthreads();
        }
    }

    // ---- inclusive suffix scan over real neg values (pads contribute 0)
    {
        int i0 = tid, i1 = tid + THREADS;
        s_suf[i0] = (i0 < npad) ? 0.0f : s_sorted[i0];
        s_suf[i1] = (i1 < npad) ? 0.0f : s_sorted[i1];
        __syncthreads();
        for (int d = 1; d < N; d <<= 1) {
            float a0 = s_suf[i0];
            float b0 = (i0 + d < N) ? s_suf[i0 + d] : 0.0f;
            float a1 = s_suf[i1];
            float b1 = (i1 + d < N) ? s_suf[i1 + d] : 0.0f;
            __syncthreads();
            s_suf[i0] = a0 + b0;
            s_suf[i1] = a1 + b1;
            __syncthreads();
        }
    }

    // ---- per-pos contribution via binary search (upper bound of p-1)
    float acc = 0.0f;
    for (int pi = tid; pi < npos; pi += THREADS) {
        float p = s_pos[pi];
        float t = p - 1.0f;
        int lo = 0, hi = N;
        #pragma unroll
        for (int it = 0; it < 9; it++) {   // log2(512) = 9 fixed iterations
            int mid = (lo + hi) >> 1;
            if (s_sorted[mid] <= t) lo = mid + 1; else hi = mid;
        }
        int cnt = N - lo;                  // all entries > t are real (pads <= t always)
        if (cnt > 0) acc += (float)cnt * (1.0f - p) + s_suf[lo];
    }

    // ---- block reduce
    #pragma unroll
    for (int o = 16; o > 0; o >>= 1)
        acc += __shfl_down_sync(0xffffffffu, acc, o);
    if ((tid & 31) == 0) s_red[tid >> 5] = acc;
    __syncthreads();
    if (tid == 0) {
        float v = 0.0f;
        #pragma unroll
        for (int w = 0; w < THREADS / 32; w++) v += s_red[w];
        g_row_sum[row]   = v;
        g_row_pairs[row] = (long long)npos * (long long)nneg;
    }
}

// ---------------------------------------------------------------------------
// Final reduction over 512 rows.
// ---------------------------------------------------------------------------
__global__ void __launch_bounds__(B)
finalize_kernel(float* __restrict__ out) {
    __shared__ double    ssum[B];
    __shared__ long long spair[B];
    int tid = threadIdx.x;
    ssum[tid]  = (double)g_row_sum[tid];
    spair[tid] = g_row_pairs[tid];
    __syncthreads();
    for (int s = B / 2; s > 0; s >>= 1) {
        if (tid < s) {
            ssum[tid]  += ssum[tid + s];
            spair[tid] += spair[tid + s];
        }
        __syncthreads();
    }
    if (tid == 0) {
        long long np = spair[0];
        out[0] = (np > 0) ? (float)(ssum[0] / (double)np) : 0.0f;
    }
}

extern "C" void kernel_launch(void* const* d_in, const int* in_sizes, int n_in,
                              void* d_out, int out_size) {
    const float*        scores = (const float*)d_in[0];
    const unsigned int* labels = (const unsigned int*)d_in[1];
    float*              out    = (float*)d_out;

    detect_kernel<<<1, 32>>>(labels);
    row_kernel<<<B, THREADS>>>(scores, labels);
    finalize_kernel<<<1, B>>>(out);
}

// round 3
// speedup vs baseline: 1.1214x; 1.1214x over previous
#include <cuda_runtime.h>

#define B 512
#define N 512
#define THREADS 256

// Cross-block accumulators (zero-initialized at module load; reset by the
// last block each call so graph replays see clean state).
__device__ double             g_sum   = 0.0;
__device__ unsigned long long g_pairs = 0ULL;
__device__ unsigned int       g_done  = 0u;

__global__ void __launch_bounds__(THREADS)
fused_kernel(const float* __restrict__ scores,
             const unsigned int* __restrict__ labels,
             float* __restrict__ out) {
    __shared__ float s_sorted[N];   // sorted neg scores (pads -FLT_MAX at front)
    __shared__ float s_bufA[N];     // scan ping
    __shared__ float s_bufB[N];     // scan pong
    __shared__ float s_pos[N];      // compacted positive scores
    __shared__ int   s_nneg, s_npos;
    __shared__ float s_red[THREADS / 32];

    const int row = blockIdx.x;
    const int tid = threadIdx.x;

    // ---- dtype detection, fused: odd 32-bit words of the first 512 words of
    // the labels buffer are all-zero iff labels are int64 (values in {0,1}).
    // All blocks read the same 1KB region (L2 hit after the first block).
    const unsigned int probe = labels[2 * tid + 1];
    if (tid == 0) { s_nneg = 0; s_npos = 0; }
    const int any_odd = __syncthreads_or(probe != 0u);   // also orders the init above
    const int stride = any_odd ? 1 : 2;                  // words per label

    const float*        srow = scores + (size_t)row * N;
    const unsigned int* lrow = labels + (size_t)row * N * stride;

    // ---- load + compact (order irrelevant: negs get sorted, pos are summed)
    #pragma unroll
    for (int e = 0; e < 2; e++) {
        int i = tid + e * THREADS;
        float v = srow[i];
        unsigned int lab = lrow[(size_t)i * stride];
        if (lab == 0u) {
            s_sorted[atomicAdd(&s_nneg, 1)] = v;
        } else {
            s_pos[atomicAdd(&s_npos, 1)] = v;
        }
    }
    __syncthreads();
    const int nneg = s_nneg;
    const int npos = s_npos;
    const int npad = N - nneg;

    // front sentinels sink below every real score
    for (int i = nneg + tid; i < N; i += THREADS) s_sorted[i] = -3.4e38f;
    __syncthreads();

    // ---- bitonic sort ascending (pads end up at the front)
    for (int k = 2; k <= N; k <<= 1) {
        for (int j = k >> 1; j > 0; j >>= 1) {
            #pragma unroll
            for (int e = 0; e < 2; e++) {
                int i = tid + e * THREADS;
                int ixj = i ^ j;
                if (ixj > i) {
                    bool up = ((i & k) == 0);
                    float a = s_sorted[i], b = s_sorted[ixj];
                    if ((a > b) == up) { s_sorted[i] = b; s_sorted[ixj] = a; }
                }
            }
            __syncthreads();
        }
    }

    // ---- inclusive suffix scan over real neg values (ping-pong: 1 bar/step)
    const int i0 = tid, i1 = tid + THREADS;
    s_bufA[i0] = (i0 < npad) ? 0.0f : s_sorted[i0];
    s_bufA[i1] = (i1 < npad) ? 0.0f : s_sorted[i1];
    __syncthreads();
    float* src = s_bufA;
    float* dst = s_bufB;
    for (int d = 1; d < N; d <<= 1) {
        dst[i0] = src[i0] + ((i0 + d < N) ? src[i0 + d] : 0.0f);
        dst[i1] = src[i1] + ((i1 + d < N) ? src[i1 + d] : 0.0f);
        __syncthreads();
        float* t = src; src = dst; dst = t;
    }
    const float* suf = src;   // result lives in the last-written buffer

    // ---- per-pos contribution: binary search for upper bound of (p - 1)
    float acc = 0.0f;
    for (int pi = tid; pi < npos; pi += THREADS) {
        float p = s_pos[pi];
        float t = p - 1.0f;
        int lo = 0, hi = N;
        #pragma unroll
        for (int it = 0; it < 9; it++) {   // log2(512) fixed iterations
            int mid = (lo + hi) >> 1;
            if (s_sorted[mid] <= t) lo = mid + 1; else hi = mid;
        }
        int cnt = N - lo;                  // entries > t are all real negs
        if (cnt > 0) acc += (float)cnt * (1.0f - p) + suf[lo];
    }

    // ---- block reduce
    #pragma unroll
    for (int o = 16; o > 0; o >>= 1)
        acc += __shfl_down_sync(0xffffffffu, acc, o);
    if ((tid & 31) == 0) s_red[tid >> 5] = acc;
    __syncthreads();

    // ---- cross-block accumulate + last-block finalize
    if (tid == 0) {
        float v = 0.0f;
        #pragma unroll
        for (int w = 0; w < THREADS / 32; w++) v += s_red[w];

        atomicAdd(&g_sum, (double)v);
        atomicAdd(&g_pairs, (unsigned long long)npos * (unsigned long long)nneg);
        __threadfence();
        unsigned int ticket = atomicAdd(&g_done, 1u);
        if (ticket == B - 1) {             // last block: all adds are visible
            __threadfence();
            double    s  = atomicAdd(&g_sum, 0.0);
            long long np = (long long)atomicAdd(&g_pairs, 0ULL);
            out[0] = (np > 0) ? (float)(s / (double)np) : 0.0f;
            // reset for the next graph replay
            g_sum   = 0.0;
            g_pairs = 0ULL;
            __threadfence();
            g_done  = 0u;
        }
    }
}

extern "C" void kernel_launch(void* const* d_in, const int* in_sizes, int n_in,
                              void* d_out, int out_size) {
    const float*        scores = (const float*)d_in[0];
    const unsigned int* labels = (const unsigned int*)d_in[1];
    float*              out    = (float*)d_out;

    fused_kernel<<<B, THREADS>>>(scores, labels, out);
}

// round 4
// speedup vs baseline: 1.4485x; 1.2917x over previous
#include <cuda_runtime.h>

#define B 512
#define N 512
#define THREADS 256
#define FULL 0xffffffffu

// Cross-block accumulators (zero at load; last block resets for graph replay).
__device__ double             g_sum   = 0.0;
__device__ unsigned long long g_pairs = 0ULL;
__device__ unsigned int       g_done  = 0u;

// Bitonic compare-exchange for an element held in a register, partner in-warp.
__device__ __forceinline__ void warp_step(float& e, int i, int k, int j) {
    float p = __shfl_xor_sync(FULL, e, j);
    bool up = ((i & k) == 0);
    bool lower = ((i & j) == 0);
    float mn = fminf(e, p), mx = fmaxf(e, p);
    e = (up == lower) ? mn : mx;
}

__global__ void __launch_bounds__(THREADS)
fused_kernel(const float* __restrict__ scores,
             const unsigned int* __restrict__ labels,
             float* __restrict__ out) {
    __shared__ float s_sorted[N];   // compaction staging, then final sorted array
    __shared__ float s_suf[N];      // sort exchange (odd), then suffix sums
    __shared__ float s_swap[N];     // sort exchange (even)
    __shared__ float s_pos[N];      // compacted positive scores
    __shared__ int   s_nneg, s_npos;
    __shared__ float s_gt[16];      // scan group totals
    __shared__ float s_red[THREADS / 32];

    const int row  = blockIdx.x;
    const int tid  = threadIdx.x;
    const int lane = tid & 31;
    const int wrp  = tid >> 5;

    // ---- dtype detect (odd words of first 1KB all-zero <=> int64 labels)
    const unsigned int probe = labels[2 * tid + 1];
    if (tid == 0) { s_nneg = 0; s_npos = 0; }
    const int any_odd = __syncthreads_or(probe != 0u);   // bar #1 (also orders init)
    const int stride = any_odd ? 1 : 2;

    const float*        srow = scores + (size_t)row * N;
    const unsigned int* lrow = labels + (size_t)row * N * stride;

    // ---- load + compact
    #pragma unroll
    for (int e = 0; e < 2; e++) {
        int i = tid + e * THREADS;
        float v = srow[i];
        unsigned int lab = lrow[(size_t)i * stride];
        if (lab == 0u) s_sorted[atomicAdd(&s_nneg, 1)] = v;
        else           s_pos   [atomicAdd(&s_npos, 1)] = v;
    }
    __syncthreads();                                      // bar #2
    const int nneg = s_nneg;
    const int npos = s_npos;
    const int npad = N - nneg;

    for (int i = nneg + tid; i < N; i += THREADS) s_sorted[i] = -3.4e38f;
    __syncthreads();                                      // bar #3

    // ---- registers: e0 = elem[tid], e1 = elem[tid+256]
    float e0 = s_sorted[tid];
    float e1 = s_sorted[tid + 256];

    // ---- bitonic sort ascending, hybrid shfl/smem
    // k = 2..32: every step fully in-warp (j <= 16)
    #pragma unroll
    for (int k = 2; k <= 32; k <<= 1) {
        #pragma unroll
        for (int j = k >> 1; j >= 1; j >>= 1) {
            warp_step(e0, tid,       k, j);
            warp_step(e1, tid + 256, k, j);
        }
    }

    // k = 64..512: j in {256}=local, {128,64,32}=smem cross-warp, {16..1}=shfl
    int phase = 0;
    #pragma unroll
    for (int k = 64; k <= 512; k <<= 1) {
        #pragma unroll
        for (int j = k >> 1; j >= 32; j >>= 1) {
            if (j == 256) {
                // partner of e0 (idx tid, lower) is e1 (idx tid+256); k=512 -> up
                float mn = fminf(e0, e1), mx = fmaxf(e0, e1);
                e0 = mn; e1 = mx;
            } else {
                float* buf = (phase & 1) ? s_suf : s_swap;
                phase++;
                buf[tid] = e0;
                buf[tid + 256] = e1;
                __syncthreads();                          // 1 bar per cross step (x9)
                float p0 = buf[tid ^ j];
                float p1 = buf[(tid ^ j) + 256];
                bool up0 = ((tid & k) == 0);
                bool up1 = (((tid + 256) & k) == 0);
                bool lo  = ((tid & j) == 0);              // same for both elems (j<=128)
                e0 = (up0 == lo) ? fminf(e0, p0) : fmaxf(e0, p0);
                e1 = (up1 == lo) ? fminf(e1, p1) : fmaxf(e1, p1);
            }
        }
        #pragma unroll
        for (int j = 16; j >= 1; j >>= 1) {
            warp_step(e0, tid,       k, j);
            warp_step(e1, tid + 256, k, j);
        }
    }

    // ---- suffix scan of neg values (pads at indices < npad contribute 0)
    float s0 = (tid < npad)       ? 0.0f : e0;
    float s1 = (tid + 256 < npad) ? 0.0f : e1;
    #pragma unroll
    for (int o = 1; o < 32; o <<= 1) {
        float t0 = __shfl_down_sync(FULL, s0, o);
        float t1 = __shfl_down_sync(FULL, s1, o);
        if (lane + o < 32) { s0 += t0; s1 += t1; }
    }
    // group g covers indices [32g, 32g+31]; e0 group = wrp, e1 group = 8+wrp
    s_sorted[tid]       = e0;        // publish sorted array for binary search
    s_sorted[tid + 256] = e1;
    if (lane == 0) { s_gt[wrp] = s0; s_gt[8 + wrp] = s1; }
    __syncthreads();                                      // bar (group totals + sorted)

    float off0 = 0.0f, off1 = 0.0f;
    for (int g = wrp + 1;     g < 16; g++) off0 += s_gt[g];
    for (int g = 8 + wrp + 1; g < 16; g++) off1 += s_gt[g];
    s_suf[tid]       = s0 + off0;    // inclusive suffix sums
    s_suf[tid + 256] = s1 + off1;
    __syncthreads();                                      // bar (suffix published)

    // ---- per-pos: binary search upper bound of (p - 1) in sorted array
    float acc = 0.0f;
    for (int pi = tid; pi < npos; pi += THREADS) {
        float p = s_pos[pi];
        float t = p - 1.0f;
        int lo = 0, hi = N;
        #pragma unroll
        for (int it = 0; it < 9; it++) {
            int mid = (lo + hi) >> 1;
            if (s_sorted[mid] <= t) lo = mid + 1; else hi = mid;
        }
        int cnt = N - lo;            // all entries > t are real negs (pads <= t)
        if (cnt > 0) acc += (float)cnt * (1.0f - p) + s_suf[lo];
    }

    // ---- block reduce
    #pragma unroll
    for (int o = 16; o > 0; o >>= 1)
        acc += __shfl_down_sync(FULL, acc, o);
    if (lane == 0) s_red[wrp] = acc;
    __syncthreads();                                      // bar

    // ---- cross-block accumulate + last-block finalize
    if (tid == 0) {
        float v = 0.0f;
        #pragma unroll
        for (int w = 0; w < THREADS / 32; w++) v += s_red[w];

        atomicAdd(&g_sum, (double)v);
        atomicAdd(&g_pairs, (unsigned long long)npos * (unsigned long long)nneg);
        __threadfence();
        unsigned int ticket = atomicAdd(&g_done, 1u);
        if (ticket == B - 1) {
            __threadfence();
            double    s  = atomicAdd(&g_sum, 0.0);
            long long np = (long long)atomicAdd(&g_pairs, 0ULL);
            out[0] = (np > 0) ? (float)(s / (double)np) : 0.0f;
            g_sum   = 0.0;
            g_pairs = 0ULL;
            __threadfence();
            g_done  = 0u;
        }
    }
}

extern "C" void kernel_launch(void* const* d_in, const int* in_sizes, int n_in,
                              void* d_out, int out_size) {
    const float*        scores = (const float*)d_in[0];
    const unsigned int* labels = (const unsigned int*)d_in[1];
    float*              out    = (float*)d_out;

    fused_kernel<<<B, THREADS>>>(scores, labels, out);
}

// round 5
// speedup vs baseline: 1.4521x; 1.0025x over previous
#include <cuda_runtime.h>

#define B 512
#define N 512
#define THREADS 256
#define NB 512
#define FULL 0xffffffffu

// Cross-block accumulators (zero at load; last block resets for graph replay).
__device__ double             g_sum   = 0.0;
__device__ unsigned long long g_pairs = 0ULL;
__device__ unsigned int       g_done  = 0u;

// Monotone non-decreasing float -> bucket map. Clamped ends are safe: the
// query checks the threshold's own bucket exactly.
__device__ __forceinline__ int bucket_of(float q) {
    float f = (q + 8.0f) * 32.0f;
    f = fminf(fmaxf(f, 0.0f), 511.0f);
    return (int)f;                       // trunc == floor (f >= 0)
}

__global__ void __launch_bounds__(THREADS)
fused_kernel(const float* __restrict__ scores,
             const unsigned int* __restrict__ labels,
             float* __restrict__ out) {
    __shared__ int   s_cnt[NB];      // per-bucket neg count
    __shared__ float s_sum[NB];      // per-bucket neg sum
    __shared__ int   s_start[NB];    // excl suffix count = count(bucket > b) = seg start
    __shared__ float s_ssum[NB];     // excl suffix sum   = sum(bucket > b)
    __shared__ int   s_cur[NB];      // scatter cursors
    __shared__ float s_scat[N];      // negs, descending-bucket order
    __shared__ float s_pos[N];       // compacted positive scores
    __shared__ int   s_npos;
    __shared__ float s_gtc[16], s_gts[16];
    __shared__ float s_red[THREADS / 32];

    const int row  = blockIdx.x;
    const int tid  = threadIdx.x;
    const int lane = tid & 31;
    const int wrp  = tid >> 5;

    // ---- zero histograms + dtype detect (1 bar orders both)
    s_cnt[tid] = 0;  s_cnt[tid + 256] = 0;
    s_sum[tid] = 0.f; s_sum[tid + 256] = 0.f;
    if (tid == 0) s_npos = 0;
    const unsigned int probe = labels[2 * tid + 1];
    const int any_odd = __syncthreads_or(probe != 0u);        // bar 1
    const int stride = any_odd ? 1 : 2;

    const float*        srow = scores + (size_t)row * N;
    const unsigned int* lrow = labels + (size_t)row * N * stride;

    // ---- load + classify + histogram (keep negs in registers for scatter)
    float v[2]; int bk[2]; bool isneg[2];
    #pragma unroll
    for (int e = 0; e < 2; e++) {
        int i = tid + e * THREADS;
        float q = srow[i];
        unsigned int lab = lrow[(size_t)i * stride];
        v[e] = q;
        isneg[e] = (lab == 0u);
        if (isneg[e]) {
            int b = bucket_of(q);
            bk[e] = b;
            atomicAdd(&s_cnt[b], 1);
            atomicAdd(&s_sum[b], q);
        } else {
            bk[e] = 0;
            s_pos[atomicAdd(&s_npos, 1)] = q;
        }
    }
    __syncthreads();                                          // bar 2
    const int npos = s_npos;
    const int nneg = N - npos;

    // ---- suffix scan over 512 buckets: thread owns b0=tid, b1=tid+256.
    // Warp-level inclusive suffix scan within each 32-bucket group (5 steps),
    // then 16 group totals combined through smem.
    float c0 = (float)s_cnt[tid],       c1 = (float)s_cnt[tid + 256];
    float m0 = s_sum[tid],              m1 = s_sum[tid + 256];
    float ic0 = c0, ic1 = c1, is0 = m0, is1 = m1;
    #pragma unroll
    for (int o = 1; o < 32; o <<= 1) {
        float a = __shfl_down_sync(FULL, ic0, o);
        float b = __shfl_down_sync(FULL, is0, o);
        float c = __shfl_down_sync(FULL, ic1, o);
        float d = __shfl_down_sync(FULL, is1, o);
        if (lane + o < 32) { ic0 += a; is0 += b; ic1 += c; is1 += d; }
    }
    if (lane == 0) {                     // lane0 holds the full group total
        s_gtc[wrp]     = ic0;  s_gts[wrp]     = is0;
        s_gtc[8 + wrp] = ic1;  s_gts[8 + wrp] = is1;
    }
    __syncthreads();                                          // bar 3
    float oc0 = 0.f, os0 = 0.f, oc1 = 0.f, os1 = 0.f;
    for (int g = wrp + 1;     g < 16; g++) { oc0 += s_gtc[g]; os0 += s_gts[g]; }
    for (int g = 9 + wrp;     g < 16; g++) { oc1 += s_gtc[g]; os1 += s_gts[g]; }
    // exclusive suffix (strictly greater buckets); counts <= 512 are exact in fp32
    int   ex0 = (int)(ic0 + oc0 - c0);
    int   ex1 = (int)(ic1 + oc1 - c1);
    s_start[tid]       = ex0;  s_ssum[tid]       = is0 + os0 - m0;
    s_start[tid + 256] = ex1;  s_ssum[tid + 256] = is1 + os1 - m1;
    s_cur[tid]       = ex0;
    s_cur[tid + 256] = ex1;
    __syncthreads();                                          // bar 4

    // ---- counting-sort scatter of negs (descending bucket order)
    #pragma unroll
    for (int e = 0; e < 2; e++) {
        if (isneg[e]) s_scat[atomicAdd(&s_cur[bk[e]], 1)] = v[e];
    }
    __syncthreads();                                          // bar 5

    // ---- per-pos query: base from suffix tables + exact in-bucket scan
    float acc = 0.0f;
    for (int pi = tid; pi < npos; pi += THREADS) {
        float p = s_pos[pi];
        float t = p - 1.0f;
        int b = bucket_of(t);
        float cg = (float)s_start[b];    // negs with bucket > b  =>  q > t
        float sg = s_ssum[b];
        int st = s_start[b];
        int en = st + s_cnt[b];
        for (int j = st; j < en; j++) {  // bucket b: exact comparison
            float q = s_scat[j];
            if (q > t) { cg += 1.0f; sg += q; }
        }
        acc += cg * (1.0f - p) + sg;
    }

    // ---- block reduce
    #pragma unroll
    for (int o = 16; o > 0; o >>= 1)
        acc += __shfl_down_sync(FULL, acc, o);
    if (lane == 0) s_red[wrp] = acc;
    __syncthreads();                                          // bar 6

    // ---- cross-block accumulate + last-block finalize
    if (tid == 0) {
        float vsum = 0.0f;
        #pragma unroll
        for (int w = 0; w < THREADS / 32; w++) vsum += s_red[w];

        atomicAdd(&g_sum, (double)vsum);
        atomicAdd(&g_pairs, (unsigned long long)npos * (unsigned long long)nneg);
        __threadfence();
        unsigned int ticket = atomicAdd(&g_done, 1u);
        if (ticket == B - 1) {
            __threadfence();
            double    s  = atomicAdd(&g_sum, 0.0);
            long long np = (long long)atomicAdd(&g_pairs, 0ULL);
            out[0] = (np > 0) ? (float)(s / (double)np) : 0.0f;
            g_sum   = 0.0;
            g_pairs = 0ULL;
            __threadfence();
            g_done  = 0u;
        }
    }
}

extern "C" void kernel_launch(void* const* d_in, const int* in_sizes, int n_in,
                              void* d_out, int out_size) {
    const float*        scores = (const float*)d_in[0];
    const unsigned int* labels = (const unsigned int*)d_in[1];
    float*              out    = (float*)d_out;

    fused_kernel<<<B, THREADS>>>(scores, labels, out);
}